// round 13
// baseline (speedup 1.0000x reference)
#include <cuda_runtime.h>
#include <math.h>
#include <float.h>

#define N      1024
#define FIN    512
#define FOUT   128
#define NT     16     // j-tiles of 64 (K2)
#define WCHUNK 64     // W k-chunk staged in smem (K1)

// Scratch (no allocations allowed)
__device__ float g_h[N * FOUT];            // embedding
__device__ float g_n[N];                   // row squared norms
__device__ float g_ppos[NT * N];           // per-j-tile partial max of (n_j - 2*dot)
__device__ float g_pneg[NT * N];           // per-j-tile partial min

// packed f32x2 helpers (ptxas will not auto-fuse FFMA2; must come from PTX)
__device__ __forceinline__ unsigned long long pk2(float lo, float hi) {
  unsigned long long r;
  asm("mov.b64 %0, {%1, %2};" : "=l"(r) : "f"(lo), "f"(hi));
  return r;
}
__device__ __forceinline__ unsigned long long dup2(float v) {
  unsigned long long r;
  asm("mov.b64 %0, {%1, %1};" : "=l"(r) : "f"(v));
  return r;
}
__device__ __forceinline__ void fma2(unsigned long long& d,
                                     unsigned long long a, unsigned long long b) {
  asm("fma.rn.f32x2 %0, %1, %2, %0;" : "+l"(d) : "l"(a), "l"(b));
}
__device__ __forceinline__ void unpk2(unsigned long long v, float& lo, float& hi) {
  asm("mov.b64 {%0, %1}, %2;" : "=f"(lo), "=f"(hi) : "l"(v));
}

// ---------------------------------------------------------------------------
// K1: fused h = inp@W + b and row norms. No K-split, no partial round-trip.
// Grid 128 blocks (8 rows each), 256 thr = 32 col-quads(tx) x 8 rows(ty).
// W staged in smem in 64-k chunks (32KB); input rows staged once (16KB).
// ---------------------------------------------------------------------------
__global__ __launch_bounds__(256) void k_linear(
    const float* __restrict__ inp, const float* __restrict__ W,
    const float* __restrict__ b) {
  __shared__ __align__(16) float sIn[8][FIN];       // 16KB
  __shared__ __align__(16) float sW[WCHUNK][FOUT];  // 32KB

  const int tid = threadIdx.x;
  const int tx = tid & 31;   // col quad -> cols tx*4..+3
  const int ty = tid >> 5;   // row (== warp id)
  const int row0 = blockIdx.x * 8;

  // stage 8x512 input rows: 1024 float4, 4 per thread
  {
    const float4* gi4 = (const float4*)(inp + (size_t)row0 * FIN);
    float4* s4 = (float4*)&sIn[0][0];
#pragma unroll
    for (int t = 0; t < 4; t++) s4[tid + t * 256] = gi4[tid + t * 256];
  }

  unsigned long long acc2[2] = {0ull, 0ull};

  for (int ch = 0; ch < FIN / WCHUNK; ch++) {
    __syncthreads();
    // stage W chunk: 64 k x 128 cols = 2048 float4, 8 per thread
    const float4* gw4 = (const float4*)(W + (size_t)ch * WCHUNK * FOUT);
    float4* sw4 = (float4*)&sW[0][0];
#pragma unroll
    for (int t = 0; t < 8; t++) sw4[tid + t * 256] = gw4[tid + t * 256];
    __syncthreads();

#pragma unroll 8
    for (int k = 0; k < WCHUNK; k++) {
      float4 w = *(const float4*)&sW[k][tx * 4];
      unsigned long long w01 = pk2(w.x, w.y);
      unsigned long long w23 = pk2(w.z, w.w);
      unsigned long long ad = dup2(sIn[ty][ch * WCHUNK + k]);  // warp broadcast
      fma2(acc2[0], ad, w01);
      fma2(acc2[1], ad, w23);
    }
  }

  float a0, a1, a2, a3;
  unpk2(acc2[0], a0, a1);
  unpk2(acc2[1], a2, a3);
  float4 bb = ((const float4*)b)[tx];
  a0 += bb.x; a1 += bb.y; a2 += bb.z; a3 += bb.w;

  const int row = row0 + ty;
  ((float4*)g_h)[row * (FOUT / 4) + tx] = make_float4(a0, a1, a2, a3);

  float s = a0 * a0 + a1 * a1 + a2 * a2 + a3 * a3;
#pragma unroll
  for (int off = 16; off; off >>= 1) s += __shfl_xor_sync(0xffffffffu, s, off);
  if (tx == 0) g_n[row] = s;
}

// ---------------------------------------------------------------------------
// K2: fused Gram tile + hardest-pos/neg reduction (f32x2 packed inner).
// Tile 64(i) x 64(j), grid (16,16), block 256 = 16(tx:j) x 16(ty:i), micro 4x4.
// ---------------------------------------------------------------------------
__global__ __launch_bounds__(256) void k_dist(const int* __restrict__ targets) {
  __shared__ __align__(16) float sA[64][68];  // [f_local][i_local], pad 68
  __shared__ __align__(16) float sB[64][68];  // [f_local][j_local]
  __shared__ float sNB[64];
  __shared__ int sTA[64], sTB[64];

  const int tid = threadIdx.x;
  const int tx = tid & 15;           // j micro position
  const int ty = tid >> 4;           // i micro position
  const int j0 = blockIdx.x * 64;
  const int i0 = blockIdx.y * 64;

  if (tid < 64) {
    sNB[tid] = g_n[j0 + tid];
    sTA[tid] = targets[i0 + tid];
    sTB[tid] = targets[j0 + tid];
  }

  unsigned long long acc2[4][2];  // [ii][j pair]
#pragma unroll
  for (int ii = 0; ii < 4; ii++) { acc2[ii][0] = 0ull; acc2[ii][1] = 0ull; }

  const int lr = tid >> 2;  // row 0..63 for staging loads
  const int lq = tid & 3;   // quad group

  for (int kc = 0; kc < 2; kc++) {
    __syncthreads();  // smem reuse barrier (also orders sNB/sTA/sTB writes)
#pragma unroll
    for (int l = 0; l < 4; l++) {
      int q = lq + l * 4;
      float4 va = ((const float4*)g_h)[(i0 + lr) * (FOUT / 4) + kc * 16 + q];
      sA[q * 4 + 0][lr] = va.x; sA[q * 4 + 1][lr] = va.y;
      sA[q * 4 + 2][lr] = va.z; sA[q * 4 + 3][lr] = va.w;
      float4 vb = ((const float4*)g_h)[(j0 + lr) * (FOUT / 4) + kc * 16 + q];
      sB[q * 4 + 0][lr] = vb.x; sB[q * 4 + 1][lr] = vb.y;
      sB[q * 4 + 2][lr] = vb.z; sB[q * 4 + 3][lr] = vb.w;
    }
    __syncthreads();

#pragma unroll 8
    for (int f = 0; f < 64; f++) {
      float4 av = *(const float4*)&sA[f][ty * 4];
      float4 bv = *(const float4*)&sB[f][tx * 4];
      unsigned long long b01 = pk2(bv.x, bv.y);
      unsigned long long b23 = pk2(bv.z, bv.w);
      float ar[4] = {av.x, av.y, av.z, av.w};
#pragma unroll
      for (int ii = 0; ii < 4; ii++) {
        unsigned long long ad = dup2(ar[ii]);
        fma2(acc2[ii][0], ad, b01);
        fma2(acc2[ii][1], ad, b23);
      }
    }
  }

  // Epilogue: v = n_j - 2*dot; masked max (pos, j!=i) / min (neg).
#pragma unroll
  for (int ii = 0; ii < 4; ii++) {
    float acc[4];
    unpk2(acc2[ii][0], acc[0], acc[1]);
    unpk2(acc2[ii][1], acc[2], acc[3]);
    const int i_l = ty * 4 + ii;
    const int gi = i0 + i_l;
    const int ti = sTA[i_l];
    float pmax = -FLT_MAX, nmin = FLT_MAX;
#pragma unroll
    for (int jj = 0; jj < 4; jj++) {
      const int j_l = tx * 4 + jj;
      const int gj = j0 + j_l;
      float v = sNB[j_l] - 2.f * acc[jj];
      bool same = (ti == sTB[j_l]);
      if (same) {
        if (gi != gj) pmax = fmaxf(pmax, v);
      } else {
        nmin = fminf(nmin, v);
      }
    }
    // reduce across tx (16 lanes sharing this i)
#pragma unroll
    for (int off = 8; off; off >>= 1) {
      pmax = fmaxf(pmax, __shfl_xor_sync(0xffffffffu, pmax, off));
      nmin = fminf(nmin, __shfl_xor_sync(0xffffffffu, nmin, off));
    }
    if (tx == 0) {
      g_ppos[blockIdx.x * N + gi] = pmax;
      g_pneg[blockIdx.x * N + gi] = nmin;
    }
  }
}

// ---------------------------------------------------------------------------
// K3: finalize. Merge 16 j-tile partials, sqrt, softplus, sum -> out[0].
// ---------------------------------------------------------------------------
__global__ __launch_bounds__(1024) void k_final(float* __restrict__ out) {
  const int i = threadIdx.x;
  float pmax = -FLT_MAX, nmin = FLT_MAX;
#pragma unroll
  for (int t = 0; t < NT; t++) {
    pmax = fmaxf(pmax, g_ppos[t * N + i]);
    nmin = fminf(nmin, g_pneg[t * N + i]);
  }
  const float ni = g_n[i];
  const bool haspos = (pmax > -FLT_MAX);
  const bool hasneg = (nmin < FLT_MAX);
  float sp = 0.f;  // softplus(-inf) = 0 when no positive exists
  if (haspos) {
    float hp = sqrtf(fmaxf(ni + pmax, 0.f));
    if (hasneg) {
      float hn = sqrtf(fmaxf(ni + nmin, 0.f));
      float x = hp - hn;
      sp = fmaxf(x, 0.f) + log1pf(expf(-fabsf(x)));
    } else {
      sp = INFINITY;  // softplus(+inf)
    }
  }

  // block sum of 1024 values
  __shared__ float wsum[32];
  float s = sp;
#pragma unroll
  for (int off = 16; off; off >>= 1) s += __shfl_xor_sync(0xffffffffu, s, off);
  if ((i & 31) == 0) wsum[i >> 5] = s;
  __syncthreads();
  if (i < 32) {
    float t = wsum[i];
#pragma unroll
    for (int off = 16; off; off >>= 1) t += __shfl_xor_sync(0xffffffffu, t, off);
    if (i == 0) out[0] = t;
  }
}

// ---------------------------------------------------------------------------
extern "C" void kernel_launch(void* const* d_in, const int* in_sizes, int n_in,
                              void* d_out, int out_size) {
  const float* inp     = (const float*)d_in[0];
  const int*   targets = (const int*)d_in[1];
  const float* W       = (const float*)d_in[2];
  const float* b       = (const float*)d_in[3];
  float* out = (float*)d_out;

  k_linear<<<N / 8, 256>>>(inp, W, b);
  k_dist<<<dim3(NT, NT), 256>>>(targets);
  k_final<<<1, 1024>>>(out);
}

// round 15
// speedup vs baseline: 1.4385x; 1.4385x over previous
#include <cuda_runtime.h>
#include <math.h>
#include <float.h>

#define N      1024
#define FIN    512
#define FOUT   128
#define NT     16     // 64-row tiles (K2)
#define NBLK   (NT * (NT + 1) / 2)   // 136 triangular tiles
#define KSLICE 16     // K-split for K1
#define KC     (FIN / KSLICE)   // 32 k per slice

// Scratch (no allocations allowed)
__device__ float g_part[KSLICE][N][FOUT];  // K1 partial sums (8MB)
__device__ float g_h[N * FOUT];            // embedding
__device__ float g_n[N];                   // row squared norms
__device__ float g_ppos[NT * N];           // per-slot partial max of (n_j - 2*dot)
__device__ float g_pneg[NT * N];           // per-slot partial min

// packed f32x2 helpers (ptxas will not auto-fuse FFMA2; must come from PTX)
__device__ __forceinline__ unsigned long long pk2(float lo, float hi) {
  unsigned long long r;
  asm("mov.b64 %0, {%1, %2};" : "=l"(r) : "f"(lo), "f"(hi));
  return r;
}
__device__ __forceinline__ unsigned long long dup2(float v) {
  unsigned long long r;
  asm("mov.b64 %0, {%1, %1};" : "=l"(r) : "f"(v));
  return r;
}
__device__ __forceinline__ void fma2(unsigned long long& d,
                                     unsigned long long a, unsigned long long b) {
  asm("fma.rn.f32x2 %0, %1, %2, %0;" : "+l"(d) : "l"(a), "l"(b));
}
__device__ __forceinline__ void unpk2(unsigned long long v, float& lo, float& hi) {
  asm("mov.b64 {%0, %1}, %2;" : "=f"(lo), "=f"(hi) : "l"(v));
}

// ---------------------------------------------------------------------------
// K1a: K-split GEMM. Block tile 64(m) x 128(n) x 32(k-slice).
// Grid (16 m-tiles, 16 k-slices) = 256 blocks. 256 thr, micro 8x4, FFMA2.
// ---------------------------------------------------------------------------
__global__ __launch_bounds__(256) void k_gemm(
    const float* __restrict__ inp, const float* __restrict__ W) {
  __shared__ __align__(16) float sA[KC][68];   // [k][row] transposed, pad 68
  __shared__ __align__(16) float sW[KC][FOUT]; // [k][col]

  const int tid = threadIdx.x;
  const int tx = tid & 31;     // col quad (0..31) -> cols tx*4..+3
  const int ty = tid >> 5;     // row octet (0..7) -> rows ty*8..+7
  const int m0 = blockIdx.x * 64;
  const int k0 = blockIdx.y * KC;

#pragma unroll
  for (int it = 0; it < 2; it++) {
    int idx = tid + it * 256;
    int row = idx >> 3;            // 0..63
    int q = idx & 7;               // k-quad 0..7
    float4 v = *(const float4*)(inp + (size_t)(m0 + row) * FIN + k0 + q * 4);
    sA[q * 4 + 0][row] = v.x; sA[q * 4 + 1][row] = v.y;
    sA[q * 4 + 2][row] = v.z; sA[q * 4 + 3][row] = v.w;
  }
#pragma unroll
  for (int it = 0; it < 4; it++) {
    int idx = tid + it * 256;
    int kk = idx >> 5;             // 0..31
    int cq = idx & 31;             // col quad
    ((float4*)&sW[kk][0])[cq] = *(const float4*)(W + (size_t)(k0 + kk) * FOUT + cq * 4);
  }
  __syncthreads();

  unsigned long long acc2[8][2];   // [row][col pair], fp32x2 packed
#pragma unroll
  for (int r = 0; r < 8; r++) { acc2[r][0] = 0ull; acc2[r][1] = 0ull; }

#pragma unroll 8
  for (int k = 0; k < KC; k++) {
    float4 w  = *(const float4*)&sW[k][tx * 4];
    unsigned long long w01 = pk2(w.x, w.y);
    unsigned long long w23 = pk2(w.z, w.w);
    float4 a0 = *(const float4*)&sA[k][ty * 8];      // warp broadcast
    float4 a1 = *(const float4*)&sA[k][ty * 8 + 4];  // warp broadcast
    float ar[8] = {a0.x, a0.y, a0.z, a0.w, a1.x, a1.y, a1.z, a1.w};
#pragma unroll
    for (int r = 0; r < 8; r++) {
      unsigned long long ad = dup2(ar[r]);
      fma2(acc2[r][0], ad, w01);
      fma2(acc2[r][1], ad, w23);
    }
  }

#pragma unroll
  for (int r = 0; r < 8; r++) {
    float c0, c1, c2, c3;
    unpk2(acc2[r][0], c0, c1);
    unpk2(acc2[r][1], c2, c3);
    *(float4*)&g_part[blockIdx.y][m0 + ty * 8 + r][tx * 4] =
        make_float4(c0, c1, c2, c3);
  }
}

// ---------------------------------------------------------------------------
// K1b: reduce 16 K-slices + bias -> h, plus row squared norms.
// ---------------------------------------------------------------------------
__global__ __launch_bounds__(128) void k_reduce(const float* __restrict__ b) {
  const int row = blockIdx.x;
  const int col = threadIdx.x;
  float s = b[col];
#pragma unroll
  for (int t = 0; t < KSLICE; t++) s += g_part[t][row][col];
  g_h[row * FOUT + col] = s;

  float sq = s * s;
#pragma unroll
  for (int off = 16; off; off >>= 1) sq += __shfl_xor_sync(0xffffffffu, sq, off);
  __shared__ float ws[4];
  if ((col & 31) == 0) ws[col >> 5] = sq;
  __syncthreads();
  if (col == 0) g_n[row] = ws[0] + ws[1] + ws[2] + ws[3];
}

// ---------------------------------------------------------------------------
// K2: symmetric Gram — only upper-triangle tiles (r<=c), 136 blocks.
// Block (r,c) serves anchors in tile r (slot c) AND, if r<c, anchors in
// tile c (slot r). Tile 64x64, 256 thr = 16(tx:j) x 16(ty:i), micro 4x4.
// ---------------------------------------------------------------------------
__global__ __launch_bounds__(256) void k_dist(const int* __restrict__ targets) {
  __shared__ __align__(16) float sA[64][68];  // [f][i_local]
  __shared__ __align__(16) float sB[64][68];  // [f][j_local]
  __shared__ float sNA[64], sNB[64];
  __shared__ int sTA[64], sTB[64];
  __shared__ float rp[16][64], rn[16][64];    // cross-ty reduce (side 2)

  const int tid = threadIdx.x;
  const int tx = tid & 15;           // j micro position
  const int ty = tid >> 4;           // i micro position

  // decode triangular (r, c), r <= c
  int r = 0, rem = blockIdx.x;
  while (rem >= NT - r) { rem -= NT - r; r++; }
  const int c = r + rem;
  const int i0 = r * 64;
  const int j0 = c * 64;

  if (tid < 64) {
    sNA[tid] = g_n[i0 + tid];
    sNB[tid] = g_n[j0 + tid];
    sTA[tid] = targets[i0 + tid];
    sTB[tid] = targets[j0 + tid];
  }

  unsigned long long acc2[4][2];  // [ii][j pair]
#pragma unroll
  for (int ii = 0; ii < 4; ii++) { acc2[ii][0] = 0ull; acc2[ii][1] = 0ull; }

  const int lr = tid >> 2;  // row 0..63 for staging loads
  const int lq = tid & 3;   // quad group

  for (int kc = 0; kc < 2; kc++) {
    __syncthreads();  // smem reuse barrier (also orders sN*/sT* writes)
#pragma unroll
    for (int l = 0; l < 4; l++) {
      int q = lq + l * 4;
      float4 va = ((const float4*)g_h)[(i0 + lr) * (FOUT / 4) + kc * 16 + q];
      sA[q * 4 + 0][lr] = va.x; sA[q * 4 + 1][lr] = va.y;
      sA[q * 4 + 2][lr] = va.z; sA[q * 4 + 3][lr] = va.w;
      float4 vb = ((const float4*)g_h)[(j0 + lr) * (FOUT / 4) + kc * 16 + q];
      sB[q * 4 + 0][lr] = vb.x; sB[q * 4 + 1][lr] = vb.y;
      sB[q * 4 + 2][lr] = vb.z; sB[q * 4 + 3][lr] = vb.w;
    }
    __syncthreads();

#pragma unroll 8
    for (int f = 0; f < 64; f++) {
      float4 av = *(const float4*)&sA[f][ty * 4];
      float4 bv = *(const float4*)&sB[f][tx * 4];
      unsigned long long b01 = pk2(bv.x, bv.y);
      unsigned long long b23 = pk2(bv.z, bv.w);
      float ar[4] = {av.x, av.y, av.z, av.w};
#pragma unroll
      for (int ii = 0; ii < 4; ii++) {
        unsigned long long ad = dup2(ar[ii]);
        fma2(acc2[ii][0], ad, b01);
        fma2(acc2[ii][1], ad, b23);
      }
    }
  }

  float acc[4][4];
#pragma unroll
  for (int ii = 0; ii < 4; ii++) {
    unpk2(acc2[ii][0], acc[ii][0], acc[ii][1]);
    unpk2(acc2[ii][1], acc[ii][2], acc[ii][3]);
  }

  // ---- side 1: anchors = rows of tile r, over j in tile c -> slot c ----
#pragma unroll
  for (int ii = 0; ii < 4; ii++) {
    const int i_l = ty * 4 + ii;
    const int gi = i0 + i_l;
    const int ti = sTA[i_l];
    float pmax = -FLT_MAX, nmin = FLT_MAX;
#pragma unroll
    for (int jj = 0; jj < 4; jj++) {
      const int j_l = tx * 4 + jj;
      const int gj = j0 + j_l;
      float v = sNB[j_l] - 2.f * acc[ii][jj];
      if (ti == sTB[j_l]) {
        if (gi != gj) pmax = fmaxf(pmax, v);
      } else {
        nmin = fminf(nmin, v);
      }
    }
#pragma unroll
    for (int off = 8; off; off >>= 1) {
      pmax = fmaxf(pmax, __shfl_xor_sync(0xffffffffu, pmax, off));
      nmin = fminf(nmin, __shfl_xor_sync(0xffffffffu, nmin, off));
    }
    if (tx == 0) {
      g_ppos[c * N + gi] = pmax;
      g_pneg[c * N + gi] = nmin;
    }
  }

  // ---- side 2: anchors = cols of tile c, over i in tile r -> slot r ----
  if (r != c) {
#pragma unroll
    for (int jj = 0; jj < 4; jj++) {
      const int j_l = tx * 4 + jj;
      const int tj = sTB[j_l];
      float pmax = -FLT_MAX, nmin = FLT_MAX;
#pragma unroll
      for (int ii = 0; ii < 4; ii++) {
        const int i_l = ty * 4 + ii;
        float v = sNA[i_l] - 2.f * acc[ii][jj];
        if (sTA[i_l] == tj) pmax = fmaxf(pmax, v);
        else                nmin = fminf(nmin, v);
      }
      rp[ty][j_l] = pmax;
      rn[ty][j_l] = nmin;
    }
    __syncthreads();
    if (tid < 64) {
      float pmax = -FLT_MAX, nmin = FLT_MAX;
#pragma unroll
      for (int t = 0; t < 16; t++) {
        pmax = fmaxf(pmax, rp[t][tid]);
        nmin = fminf(nmin, rn[t][tid]);
      }
      g_ppos[r * N + j0 + tid] = pmax;
      g_pneg[r * N + j0 + tid] = nmin;
    }
  }
}

// ---------------------------------------------------------------------------
// K3: finalize. Merge 16 slot partials, sqrt, softplus, sum -> out[0].
// ---------------------------------------------------------------------------
__global__ __launch_bounds__(1024) void k_final(float* __restrict__ out) {
  const int i = threadIdx.x;
  float pmax = -FLT_MAX, nmin = FLT_MAX;
#pragma unroll
  for (int t = 0; t < NT; t++) {
    pmax = fmaxf(pmax, g_ppos[t * N + i]);
    nmin = fminf(nmin, g_pneg[t * N + i]);
  }
  const float ni = g_n[i];
  const bool haspos = (pmax > -FLT_MAX);
  const bool hasneg = (nmin < FLT_MAX);
  float sp = 0.f;  // softplus(-inf) = 0 when no positive exists
  if (haspos) {
    float hp = sqrtf(fmaxf(ni + pmax, 0.f));
    if (hasneg) {
      float hn = sqrtf(fmaxf(ni + nmin, 0.f));
      float x = hp - hn;
      sp = fmaxf(x, 0.f) + log1pf(expf(-fabsf(x)));
    } else {
      sp = INFINITY;  // softplus(+inf)
    }
  }

  __shared__ float wsum[32];
  float s = sp;
#pragma unroll
  for (int off = 16; off; off >>= 1) s += __shfl_xor_sync(0xffffffffu, s, off);
  if ((i & 31) == 0) wsum[i >> 5] = s;
  __syncthreads();
  if (i < 32) {
    float t = wsum[i];
#pragma unroll
    for (int off = 16; off; off >>= 1) t += __shfl_xor_sync(0xffffffffu, t, off);
    if (i == 0) out[0] = t;
  }
}

// ---------------------------------------------------------------------------
extern "C" void kernel_launch(void* const* d_in, const int* in_sizes, int n_in,
                              void* d_out, int out_size) {
  const float* inp     = (const float*)d_in[0];
  const int*   targets = (const int*)d_in[1];
  const float* W       = (const float*)d_in[2];
  const float* b       = (const float*)d_in[3];
  float* out = (float*)d_out;

  k_gemm<<<dim3(16, KSLICE), 256>>>(inp, W);
  k_reduce<<<N, 128>>>(b);
  k_dist<<<NBLK, 256>>>(targets);
  k_final<<<1, 1024>>>(out);
}